// round 1
// baseline (speedup 1.0000x reference)
#include <cuda_runtime.h>

#define DTC 0.1f
#define NST 64      // state size N
#define DCH 128     // channels D
#define LSEQ 4096
#define BSZ 16
#define KMAX 48     // truncated convolution length (tail ~0.55^48 ~ 1e-13)
#define TL 64       // timesteps per conv block
#define HALO (KMAX - 1)        // 47
#define XROWS (TL + HALO)      // 111
#define AUGC 129               // 64 (M) + 64 (I+X) + 1 (B)

// Scratch for the per-channel convolution kernel K[k][d] (layout k-major for
// conflict-free smem loads in the conv kernel).
__device__ float g_K[KMAX * DCH];

// ---------------------------------------------------------------------------
// Prep: per channel d, solve (I - 0.05A) [Abar | Bbar0] = [(I + 0.05A) | B],
// then K_k = Cv^T Abar^k (Bbar0 * DT) for k = 0..KMAX-1.
// One block per d, 256 threads. Gauss-Jordan without pivoting: M is strongly
// diagonally dominant (diag ~ 4.2, row off-diag sum <= 3.15).
// ---------------------------------------------------------------------------
__global__ __launch_bounds__(256) void prep_kernel(const float* __restrict__ A,
                                                   const float* __restrict__ B,
                                                   const float* __restrict__ C) {
    __shared__ float M[NST][AUGC];   // 64 x 129 augmented matrix
    __shared__ float prow[AUGC];     // scaled pivot row
    __shared__ float part[4 * NST];  // matvec partials
    __shared__ float vbuf[2][NST];
    __shared__ float Cs[NST];

    const int d = blockIdx.x;
    const int t = threadIdx.x;
    const int i = t & 63;   // row owned
    const int q = t >> 6;   // column quarter (0..3)

    const float* Ad = A + (size_t)d * NST * NST;

    // Load augmented system.
    for (int idx = t; idx < NST * NST; idx += 256) {
        int r = idx >> 6, c = idx & 63;
        float a = Ad[idx];
        float eye = (r == c) ? 1.0f : 0.0f;
        M[r][c]      = eye - 0.05f * a;   // I - A*dt/2
        M[r][64 + c] = eye + 0.05f * a;   // I + A*dt/2
    }
    if (t < NST) {
        M[t][128] = B[d * NST + t];
        Cs[t]     = C[d * NST + t];
    }
    __syncthreads();

    // Gauss-Jordan elimination (2 barriers per pivot).
    for (int p = 0; p < NST; ++p) {
        float pivinv = 1.0f / M[p][p];
        float f = M[i][p];               // read before any write this pivot
        if (t < AUGC) prow[t] = M[p][t] * pivinv;
        __syncthreads();
        if (i == p) {
            for (int c = q; c < AUGC; c += 4) M[p][c] = prow[c];
        } else {
            for (int c = q; c < AUGC; c += 4) M[i][c] -= f * prow[c];
        }
        __syncthreads();
    }

    // Now M[:,64..127] = Abar, M[:,128] = inv(..) @ B  (scale by DT).
    if (t < NST) vbuf[0][t] = M[t][128] * DTC;
    __syncthreads();

    int cur = 0;
    for (int k = 0; k < KMAX; ++k) {
        // Matvec partial: v1[i] = sum_j Abar[i][j] * v0[j], split over q.
        float s = 0.0f;
#pragma unroll
        for (int jj = 0; jj < 16; ++jj) {
            int j = q * 16 + jj;
            s += M[i][64 + j] * vbuf[cur][j];
        }
        part[q * NST + i] = s;

        // K_k = Cv . v0 via warp 0.
        if (t < 32) {
            float pr = Cs[t] * vbuf[cur][t] + Cs[t + 32] * vbuf[cur][t + 32];
#pragma unroll
            for (int o = 16; o > 0; o >>= 1)
                pr += __shfl_down_sync(0xffffffffu, pr, o);
            if (t == 0) g_K[k * DCH + d] = pr;
        }
        __syncthreads();
        if (t < NST)
            vbuf[cur ^ 1][t] = part[t] + part[64 + t] + part[128 + t] + part[192 + t];
        __syncthreads();
        cur ^= 1;
    }
}

// ---------------------------------------------------------------------------
// Depthwise causal conv: y[b,l,d] = sum_{k<KMAX} K[k][d] * x[b,l-k,d].
// Block: 512 threads = 128 d-channels x 4 l-groups; TL=64 outputs per block.
// x tile (TL+HALO rows x 128 ch) + K staged in dynamic smem.
// ---------------------------------------------------------------------------
__global__ __launch_bounds__(512, 2) void conv_kernel(const float* __restrict__ x,
                                                      float* __restrict__ y) {
    extern __shared__ float smem[];
    float* xs = smem;                       // XROWS * DCH floats (56832 B)
    float* Ks = smem + XROWS * DCH;         // KMAX * DCH floats (24576 B)

    const int t  = threadIdx.x;
    const int b  = blockIdx.y;
    const int l0 = blockIdx.x * TL;
    const float* xb = x + (size_t)b * LSEQ * DCH;

    // Stage K (vectorized; g_K is 16B aligned, size divisible by 4).
    {
        const float4* src = (const float4*)g_K;
        float4* dst = (float4*)Ks;
        for (int idx = t; idx < (KMAX * DCH) / 4; idx += 512) dst[idx] = src[idx];
    }

    // Stage x tile rows [l0-HALO, l0+TL).
    const long gbase = ((long)l0 - HALO) * DCH;
    if (l0 >= HALO) {
        const float4* src = (const float4*)(xb + gbase);
        float4* dst = (float4*)xs;
#pragma unroll 4
        for (int idx = t; idx < (XROWS * DCH) / 4; idx += 512) dst[idx] = src[idx];
    } else {
        for (int idx = t; idx < XROWS * DCH; idx += 512) {
            long g = gbase + idx;
            xs[idx] = (g >= 0) ? xb[g] : 0.0f;
        }
    }
    __syncthreads();

    const int d  = t & 127;
    const int lq = t >> 7;          // 0..3, each handles 16 consecutive l
    const int RB = 16;

    float acc[16];
#pragma unroll
    for (int r = 0; r < RB; ++r) acc[r] = 0.0f;

    const int srow0 = HALO + lq * RB;   // smem row for (r=0, k=0)

#pragma unroll
    for (int kk0 = 0; kk0 < KMAX; kk0 += 4) {
        float kv[4];
#pragma unroll
        for (int j = 0; j < 4; ++j) kv[j] = Ks[(kk0 + j) * DCH + d];

        float xv[RB + 3];
        const int base = (srow0 - kk0 - 3) * DCH + d;
#pragma unroll
        for (int m = 0; m < RB + 3; ++m) xv[m] = xs[base + m * DCH];

#pragma unroll
        for (int j = 0; j < 4; ++j)
#pragma unroll
            for (int r = 0; r < RB; ++r)
                acc[r] += kv[j] * xv[3 + r - j];
    }

    float* yb = y + ((size_t)b * LSEQ + l0 + lq * RB) * DCH + d;
#pragma unroll
    for (int r = 0; r < RB; ++r) yb[r * DCH] = acc[r];
}

// ---------------------------------------------------------------------------
extern "C" void kernel_launch(void* const* d_in, const int* in_sizes, int n_in,
                              void* d_out, int out_size) {
    const float* x = (const float*)d_in[0];
    const float* A = (const float*)d_in[1];
    const float* B = (const float*)d_in[2];
    const float* C = (const float*)d_in[3];
    float* y = (float*)d_out;

    (void)in_sizes; (void)n_in; (void)out_size;

    const int conv_smem = (XROWS * DCH + KMAX * DCH) * (int)sizeof(float); // 81408 B
    cudaFuncSetAttribute(conv_kernel, cudaFuncAttributeMaxDynamicSharedMemorySize,
                         conv_smem);

    prep_kernel<<<DCH, 256>>>(A, B, C);

    dim3 grid(LSEQ / TL, BSZ);
    conv_kernel<<<grid, 512, conv_smem>>>(x, y);
}

// round 2
// speedup vs baseline: 2.2357x; 2.2357x over previous
#include <cuda_runtime.h>

#define DTC 0.1f
#define NST 64
#define DCH 128
#define LSEQ 4096
#define BSZ 16
#define KMAX 32                 // |eig(Abar)|max ~0.537 -> 0.537^32 ~ 2e-9 truncation
#define TL 128                  // timesteps per conv block
#define HALO (KMAX - 1)         // 31
#define XROWS (TL + HALO)       // 159

__device__ __align__(16) float g_K[KMAX * DCH];   // K[k][d]

// ---------------------------------------------------------------------------
// Prep v2: register-resident Gauss-Jordan on [M | P | B], M = I-0.05A,
// P = I+0.05A. One block per channel d, 256 threads. Thread (i = t&63,
// q = t>>6) owns row i, logical columns [q*32, q*32+32) (+ col 128 for q=3)
// in registers. Per pivot: only raw pivot row + pivot column go through smem
// (double buffered, ONE barrier per pivot). Then 32 Krylov steps
// v <- Abar v with Abar rows held in q=2,3 registers; K_k = Cv . v_k.
// Diagonal dominance (diag ~4.2, off-row-sum <=3.15) -> no pivoting needed.
// ---------------------------------------------------------------------------
__global__ __launch_bounds__(256) void prep_kernel(const float* __restrict__ A,
                                                   const float* __restrict__ B,
                                                   const float* __restrict__ C) {
    __shared__ __align__(16) float As[NST * 65];      // padded A tile
    __shared__ __align__(16) float prow[2][132];      // raw pivot row (129 used)
    __shared__ __align__(16) float fcol[2][NST];      // pivot column
    __shared__ __align__(16) float vbuf[NST];
    __shared__ __align__(16) float psum[2][NST];
    __shared__ __align__(16) float Cs[NST];

    const int d = blockIdx.x;
    const int t = threadIdx.x;
    const int i = t & 63;
    const int q = t >> 6;

    // Coalesced load of A[d] into padded smem (bank-conflict-free column reads).
    const float* Ad = A + (size_t)d * NST * NST;
    for (int idx = t; idx < NST * NST; idx += 256) {
        int r = idx >> 6, c = idx & 63;
        As[r * 65 + c] = Ad[idx];
    }
    if (t < NST) Cs[t] = C[d * NST + t];
    __syncthreads();

    // Registers: this thread's 32 (+1) augmented-matrix entries.
    float m[33];
    {
        const float sgn = (q < 2) ? -0.05f : 0.05f;     // M part vs P part
        const int ac0 = (q & 1) * 32;                   // A column base
#pragma unroll
        for (int j = 0; j < 32; ++j) {
            float a = As[i * 65 + ac0 + j];
            float eye = (ac0 + j == i) ? 1.0f : 0.0f;
            m[j] = fmaf(sgn, a, eye);
        }
        m[32] = (q == 3) ? B[d * NST + i] : 0.0f;
    }
    __syncthreads();

    // Gauss-Jordan, fully unrolled (static register indices), 1 barrier/pivot.
#pragma unroll
    for (int p = 0; p < NST; ++p) {
        const int bp = p & 1;
        const int qp = p >> 5;      // compile-time
        const int jp = p & 31;      // compile-time

        if (q == qp) fcol[bp][i] = m[jp];
        if (i == p) {
            float4* pw = (float4*)&prow[bp][q * 32];
#pragma unroll
            for (int jj = 0; jj < 8; ++jj)
                pw[jj] = make_float4(m[jj * 4], m[jj * 4 + 1], m[jj * 4 + 2], m[jj * 4 + 3]);
            if (q == 3) prow[bp][128] = m[32];
        }
        __syncthreads();

        float pv = fcol[bp][p];
        if (i == p) {
            float pinv = __fdividef(1.0f, pv);
#pragma unroll
            for (int j = 0; j <= 32; ++j) m[j] *= pinv;
        } else {
            float fs = __fdividef(fcol[bp][i], pv);
            const float4* pr4 = (const float4*)&prow[bp][q * 32];
#pragma unroll
            for (int jj = 0; jj < 8; ++jj) {
                float4 pv4 = pr4[jj];
                m[jj * 4]     = fmaf(-fs, pv4.x, m[jj * 4]);
                m[jj * 4 + 1] = fmaf(-fs, pv4.y, m[jj * 4 + 1]);
                m[jj * 4 + 2] = fmaf(-fs, pv4.z, m[jj * 4 + 2]);
                m[jj * 4 + 3] = fmaf(-fs, pv4.w, m[jj * 4 + 3]);
            }
            if (q == 3) m[32] = fmaf(-fs, prow[bp][128], m[32]);
        }
    }

    // Now q=2 holds Abar[i][0..31], q=3 holds Abar[i][32..63] and (M^-1 B)[i].
    if (q == 3) vbuf[i] = m[32] * DTC;   // v0 = Bbar
    __syncthreads();

    for (int k = 0; k < KMAX; ++k) {
        // K_k = Cv . v_k  (warp 0)
        if (t < 32) {
            float pr = Cs[t] * vbuf[t] + Cs[t + 32] * vbuf[t + 32];
#pragma unroll
            for (int o = 16; o > 0; o >>= 1)
                pr += __shfl_down_sync(0xffffffffu, pr, o);
            if (t == 0) g_K[k * DCH + d] = pr;
        }
        // matvec partials
        if (q >= 2) {
            const float4* v4 = (const float4*)vbuf + (q - 2) * 8;
            float s0 = 0.0f, s1 = 0.0f;
#pragma unroll
            for (int jj = 0; jj < 8; ++jj) {
                float4 vv = v4[jj];
                s0 = fmaf(m[jj * 4],     vv.x, s0);
                s1 = fmaf(m[jj * 4 + 1], vv.y, s1);
                s0 = fmaf(m[jj * 4 + 2], vv.z, s0);
                s1 = fmaf(m[jj * 4 + 3], vv.w, s1);
            }
            psum[q - 2][i] = s0 + s1;
        }
        __syncthreads();
        if (q == 0) vbuf[i] = psum[0][i] + psum[1][i];
        __syncthreads();
    }
}

// ---------------------------------------------------------------------------
// Depthwise causal conv: y[b,l,d] = sum_{k<32} K[k][d] * x[b,l-k,d].
// Block 512 thr = 32 channel-quads (lane dim, coalesced float4) x 16 l-groups.
// Each thread: 8 consecutive outputs x 4 channels, 4-tap k-chunks with
// sliding register window -> 128 FMA per 15 LDS.128 per chunk.
// ---------------------------------------------------------------------------
__global__ __launch_bounds__(512, 1) void conv_kernel(const float* __restrict__ x,
                                                      float* __restrict__ y) {
    extern __shared__ __align__(16) float smem[];
    float* xs = smem;                       // XROWS*128 floats (81408 B)
    float* Ks = smem + XROWS * DCH;         // KMAX*128 floats (16384 B)

    const int t  = threadIdx.x;
    const int b  = blockIdx.y;
    const int l0 = blockIdx.x * TL;
    const float* xb = x + (size_t)b * LSEQ * DCH;

    // Stage K.
    {
        const float4* src = (const float4*)g_K;
        float4* dst = (float4*)Ks;
        for (int idx = t; idx < (KMAX * DCH) / 4; idx += 512) dst[idx] = src[idx];
    }
    // Stage x rows [l0-HALO, l0+TL).
    const long gbase = ((long)l0 - HALO) * DCH;
    if (l0 >= HALO) {
        const float4* src = (const float4*)(xb + gbase);
        float4* dst = (float4*)xs;
#pragma unroll 5
        for (int idx = t; idx < (XROWS * DCH) / 4; idx += 512) dst[idx] = src[idx];
    } else {
        for (int idx = t; idx < XROWS * DCH; idx += 512) {
            long g = gbase + idx;
            xs[idx] = (g >= 0) ? xb[g] : 0.0f;
        }
    }
    __syncthreads();

    const int d4 = (t & 31) * 4;    // channel base (lanes -> coalesced)
    const int lt = t >> 5;          // 0..15
    const int srow0 = HALO + lt * 8;

    float4 acc[8];
#pragma unroll
    for (int r = 0; r < 8; ++r) acc[r] = make_float4(0.f, 0.f, 0.f, 0.f);

#pragma unroll
    for (int k0 = 0; k0 < KMAX; k0 += 4) {
        float4 kv[4];
#pragma unroll
        for (int j = 0; j < 4; ++j)
            kv[j] = *(const float4*)&Ks[(k0 + j) * DCH + d4];

        float4 xv[11];
        const int rbase = srow0 - k0 - 3;
#pragma unroll
        for (int mr = 0; mr < 11; ++mr)
            xv[mr] = *(const float4*)&xs[(rbase + mr) * DCH + d4];

#pragma unroll
        for (int j = 0; j < 4; ++j)
#pragma unroll
            for (int r = 0; r < 8; ++r) {
                float4 xr = xv[3 + r - j];
                acc[r].x = fmaf(kv[j].x, xr.x, acc[r].x);
                acc[r].y = fmaf(kv[j].y, xr.y, acc[r].y);
                acc[r].z = fmaf(kv[j].z, xr.z, acc[r].z);
                acc[r].w = fmaf(kv[j].w, xr.w, acc[r].w);
            }
    }

    float4* yb = (float4*)(y + ((size_t)b * LSEQ + l0 + lt * 8) * DCH + d4);
#pragma unroll
    for (int r = 0; r < 8; ++r) yb[r * (DCH / 4)] = acc[r];
}

// ---------------------------------------------------------------------------
extern "C" void kernel_launch(void* const* d_in, const int* in_sizes, int n_in,
                              void* d_out, int out_size) {
    const float* x = (const float*)d_in[0];
    const float* A = (const float*)d_in[1];
    const float* B = (const float*)d_in[2];
    const float* C = (const float*)d_in[3];
    float* y = (float*)d_out;
    (void)in_sizes; (void)n_in; (void)out_size;

    const int conv_smem = (XROWS * DCH + KMAX * DCH) * (int)sizeof(float); // 97792 B
    cudaFuncSetAttribute(conv_kernel, cudaFuncAttributeMaxDynamicSharedMemorySize,
                         conv_smem);

    prep_kernel<<<DCH, 256>>>(A, B, C);

    dim3 grid(LSEQ / TL, BSZ);
    conv_kernel<<<grid, 512, conv_smem>>>(x, y);
}